// round 1
// baseline (speedup 1.0000x reference)
#include <cuda_runtime.h>
#include <math.h>

// Problem constants
#define B_   2
#define T_   2048
#define D_   768
#define H_   12
#define DK_  64
#define MTOK (B_*T_)          // 4096

// GEMM tiling
#define BM 64
#define BN 64
#define BK 16
#define TM 4
#define TN 4
#define NTHR 256

// Scratch (allocation-free: __device__ globals)
__device__ float g_Q[MTOK*D_];
__device__ float g_K[MTOK*D_];
__device__ float g_V[MTOK*D_];
__device__ float g_attn[MTOK*D_];
// Fallback weights scratch in case d_out only holds the first output
__device__ float g_wts_fallback[(size_t)B_*H_*T_*T_];

// ---------------------------------------------------------------------------
// C[m,n] = alpha * sum_k A[m*lda+k] * B[n*ldb+k]   (NT: B row-major [N,K])
// 2-level batch: bz -> (outer, inner); pointers advanced by strides.
// ---------------------------------------------------------------------------
__global__ __launch_bounds__(NTHR) void gemm_nt(
    const float* __restrict__ A, const float* __restrict__ Bm, float* __restrict__ C,
    int K, int lda, int ldb, int ldc, float alpha, int innerCount,
    long aSO, long aSI, long bSO, long bSI, long cSO, long cSI)
{
    const int bz = blockIdx.z;
    const int bo = bz / innerCount, bi = bz % innerCount;
    A  += (long)bo*aSO + (long)bi*aSI;
    Bm += (long)bo*bSO + (long)bi*bSI;
    C  += (long)bo*cSO + (long)bi*cSI;

    __shared__ float As[BK][BM];
    __shared__ float Bs[BK][BN];

    const int tid  = threadIdx.x;
    const int row0 = blockIdx.y * BM;
    const int col0 = blockIdx.x * BN;
    const int ty = tid >> 4, tx = tid & 15;
    const int m0 = ty * TM, n0 = tx * TN;

    float acc[TM][TN];
#pragma unroll
    for (int i = 0; i < TM; i++)
#pragma unroll
        for (int j = 0; j < TN; j++) acc[i][j] = 0.0f;

    for (int k0 = 0; k0 < K; k0 += BK) {
#pragma unroll
        for (int r = 0; r < (BM*BK)/NTHR; r++) {
            int i = tid + r * NTHR;
            int m = i >> 4, k = i & 15;
            As[k][m] = A[(long)(row0 + m) * lda + (k0 + k)];
        }
#pragma unroll
        for (int r = 0; r < (BN*BK)/NTHR; r++) {
            int i = tid + r * NTHR;
            int n = i >> 4, k = i & 15;
            Bs[k][n] = Bm[(long)(col0 + n) * ldb + (k0 + k)];
        }
        __syncthreads();
#pragma unroll
        for (int k = 0; k < BK; k++) {
            float4 ra = *reinterpret_cast<const float4*>(&As[k][m0]);
            float4 rb = *reinterpret_cast<const float4*>(&Bs[k][n0]);
            float a0[4] = {ra.x, ra.y, ra.z, ra.w};
            float b0[4] = {rb.x, rb.y, rb.z, rb.w};
#pragma unroll
            for (int i = 0; i < TM; i++)
#pragma unroll
                for (int j = 0; j < TN; j++)
                    acc[i][j] = fmaf(a0[i], b0[j], acc[i][j]);
        }
        __syncthreads();
    }

#pragma unroll
    for (int i = 0; i < TM; i++) {
        float4 o;
        o.x = alpha * acc[i][0];
        o.y = alpha * acc[i][1];
        o.z = alpha * acc[i][2];
        o.w = alpha * acc[i][3];
        *reinterpret_cast<float4*>(&C[(long)(row0 + m0 + i) * ldc + col0 + n0]) = o;
    }
}

// ---------------------------------------------------------------------------
// C[m,n] = sum_k A[m*lda+k] * B[k*ldb+n]   (NN)
// ---------------------------------------------------------------------------
__global__ __launch_bounds__(NTHR) void gemm_nn(
    const float* __restrict__ A, const float* __restrict__ Bm, float* __restrict__ C,
    int K, int lda, int ldb, int ldc, int innerCount,
    long aSO, long aSI, long bSO, long bSI, long cSO, long cSI)
{
    const int bz = blockIdx.z;
    const int bo = bz / innerCount, bi = bz % innerCount;
    A  += (long)bo*aSO + (long)bi*aSI;
    Bm += (long)bo*bSO + (long)bi*bSI;
    C  += (long)bo*cSO + (long)bi*cSI;

    __shared__ float As[BK][BM];
    __shared__ float Bs[BK][BN];

    const int tid  = threadIdx.x;
    const int row0 = blockIdx.y * BM;
    const int col0 = blockIdx.x * BN;
    const int ty = tid >> 4, tx = tid & 15;
    const int m0 = ty * TM, n0 = tx * TN;

    float acc[TM][TN];
#pragma unroll
    for (int i = 0; i < TM; i++)
#pragma unroll
        for (int j = 0; j < TN; j++) acc[i][j] = 0.0f;

    for (int k0 = 0; k0 < K; k0 += BK) {
#pragma unroll
        for (int r = 0; r < (BM*BK)/NTHR; r++) {
            int i = tid + r * NTHR;
            int m = i >> 4, k = i & 15;
            As[k][m] = A[(long)(row0 + m) * lda + (k0 + k)];
        }
#pragma unroll
        for (int r = 0; r < (BN*BK)/NTHR; r++) {
            int i = tid + r * NTHR;
            int k = i >> 6, n = i & 63;        // n fastest -> coalesced
            Bs[k][n] = Bm[(long)(k0 + k) * ldb + (col0 + n)];
        }
        __syncthreads();
#pragma unroll
        for (int k = 0; k < BK; k++) {
            float4 ra = *reinterpret_cast<const float4*>(&As[k][m0]);
            float4 rb = *reinterpret_cast<const float4*>(&Bs[k][n0]);
            float a0[4] = {ra.x, ra.y, ra.z, ra.w};
            float b0[4] = {rb.x, rb.y, rb.z, rb.w};
#pragma unroll
            for (int i = 0; i < TM; i++)
#pragma unroll
                for (int j = 0; j < TN; j++)
                    acc[i][j] = fmaf(a0[i], b0[j], acc[i][j]);
        }
        __syncthreads();
    }

#pragma unroll
    for (int i = 0; i < TM; i++) {
        float4 o;
        o.x = acc[i][0]; o.y = acc[i][1]; o.z = acc[i][2]; o.w = acc[i][3];
        *reinterpret_cast<float4*>(&C[(long)(row0 + m0 + i) * ldc + col0 + n0]) = o;
    }
}

// ---------------------------------------------------------------------------
// Row softmax in place. One block (256 thr) per row of length T_=2048.
// ---------------------------------------------------------------------------
__global__ __launch_bounds__(256) void softmax_rows(float* __restrict__ W)
{
    __shared__ float sred[8];
    const long row = blockIdx.x;
    float* p = W + row * (long)T_;
    const int tid = threadIdx.x;

    float v[8];
#pragma unroll
    for (int i = 0; i < 8; i++) v[i] = p[tid + 256 * i];

    float m = v[0];
#pragma unroll
    for (int i = 1; i < 8; i++) m = fmaxf(m, v[i]);
#pragma unroll
    for (int o = 16; o > 0; o >>= 1) m = fmaxf(m, __shfl_xor_sync(0xffffffffu, m, o));
    if ((tid & 31) == 0) sred[tid >> 5] = m;
    __syncthreads();
    float bm = sred[0];
#pragma unroll
    for (int i = 1; i < 8; i++) bm = fmaxf(bm, sred[i]);
    __syncthreads();

    float s = 0.0f;
#pragma unroll
    for (int i = 0; i < 8; i++) { v[i] = __expf(v[i] - bm); s += v[i]; }
#pragma unroll
    for (int o = 16; o > 0; o >>= 1) s += __shfl_xor_sync(0xffffffffu, s, o);
    if ((tid & 31) == 0) sred[tid >> 5] = s;
    __syncthreads();
    float bs = 0.0f;
#pragma unroll
    for (int i = 0; i < 8; i++) bs += sred[i];

    const float inv = 1.0f / bs;
#pragma unroll
    for (int i = 0; i < 8; i++) p[tid + 256 * i] = v[i] * inv;
}

// ---------------------------------------------------------------------------
extern "C" void kernel_launch(void* const* d_in, const int* in_sizes, int n_in,
                              void* d_out, int out_size)
{
    const float* q  = (const float*)d_in[0];
    const float* k  = (const float*)d_in[1];
    const float* v  = (const float*)d_in[2];
    const float* Wq = (const float*)d_in[3];
    const float* Wk = (const float*)d_in[4];
    const float* Wv = (const float*)d_in[5];
    const float* Wo = (const float*)d_in[6];
    float* out = (float*)d_out;

    float *gq, *gk, *gv, *ga, *gwf;
    cudaGetSymbolAddress((void**)&gq,  g_Q);
    cudaGetSymbolAddress((void**)&gk,  g_K);
    cudaGetSymbolAddress((void**)&gv,  g_V);
    cudaGetSymbolAddress((void**)&ga,  g_attn);
    cudaGetSymbolAddress((void**)&gwf, g_wts_fallback);

    const long outElems = (long)B_ * T_ * D_;                 // 3,145,728
    const long wtsElems = (long)B_ * H_ * T_ * T_;            // 100,663,296
    // Output convention: [output | weights] concatenated. Fallback to device
    // scratch for weights if the harness only sized d_out for the first output.
    float* wts = ((long)out_size >= outElems + wtsElems) ? (out + outElems) : gwf;

    const long TT = (long)T_ * T_;

    // 1) Projections: X[4096,768] @ W[768,768]^T
    dim3 gProj(D_/BN, MTOK/BM, 1);
    gemm_nt<<<gProj, NTHR>>>(q, Wq, gq, D_, D_, D_, D_, 1.0f, 1, 0,0, 0,0, 0,0);
    gemm_nt<<<gProj, NTHR>>>(k, Wk, gk, D_, D_, D_, D_, 1.0f, 1, 0,0, 0,0, 0,0);
    gemm_nt<<<gProj, NTHR>>>(v, Wv, gv, D_, D_, D_, D_, 1.0f, 1, 0,0, 0,0, 0,0);

    // 2) Scores: per (b,h): S = (Q_h K_h^T) / 8     [2048,2048], K-dim 64
    dim3 gScore(T_/BN, T_/BM, B_*H_);
    gemm_nt<<<gScore, NTHR>>>(gq, gk, wts,
                              DK_, D_, D_, T_, 1.0f/8.0f, H_,
                              (long)T_*D_, DK_,          // A: b-stride, h-stride
                              (long)T_*D_, DK_,          // B
                              (long)H_*TT, TT);          // C

    // 3) Softmax each of B*H*T rows (in place in wts)
    softmax_rows<<<(unsigned)(B_*H_*T_), 256>>>(wts);

    // 4) attn = W @ V : per (b,h): [2048,2048] @ [2048,64]
    dim3 gAV(DK_/BN, T_/BM, B_*H_);
    gemm_nn<<<gAV, NTHR>>>(wts, gv, ga,
                           T_, T_, D_, D_, H_,
                           (long)H_*TT, TT,
                           (long)T_*D_, DK_,
                           (long)T_*D_, DK_);

    // 5) Output projection: attn[4096,768] @ W_o^T -> out
    gemm_nt<<<gProj, NTHR>>>(ga, Wo, out, D_, D_, D_, D_, 1.0f, 1, 0,0, 0,0, 0,0);
}

// round 2
// speedup vs baseline: 3.2444x; 3.2444x over previous
#include <cuda_runtime.h>
#include <math.h>
#include <stdint.h>

// Problem constants
#define B_   2
#define T_   2048
#define D_   768
#define H_   12
#define DK_  64
#define MTOK (B_*T_)          // 4096

// Scratch (allocation-free: __device__ globals)
__device__ float g_Q[MTOK*D_];
__device__ float g_K[MTOK*D_];
__device__ float g_V[MTOK*D_];
__device__ float g_attn[MTOK*D_];
__device__ float g_wts_fallback[(size_t)B_*H_*T_*T_];

// ---------------------------------------------------------------------------
// tf32 helpers
// ---------------------------------------------------------------------------
__device__ __forceinline__ uint32_t f2tf32(float x) {
    uint32_t u;
    asm("cvt.rna.tf32.f32 %0, %1;" : "=r"(u) : "f"(x));
    return u;
}

__device__ __forceinline__ void mma16n8k8(float* c, const uint32_t* a, const uint32_t* b) {
    asm volatile(
        "mma.sync.aligned.m16n8k8.row.col.f32.tf32.tf32.f32 "
        "{%0,%1,%2,%3}, {%4,%5,%6,%7}, {%8,%9}, {%0,%1,%2,%3};\n"
        : "+f"(c[0]), "+f"(c[1]), "+f"(c[2]), "+f"(c[3])
        : "r"(a[0]), "r"(a[1]), "r"(a[2]), "r"(a[3]), "r"(b[0]), "r"(b[1]));
}

// ---------------------------------------------------------------------------
// tf32 tensor-core GEMM.
//  BT = true : C[m,n] = alpha * sum_k A[m,k] * B[n,k]   (B row-major [N,K])
//  BT = false: C[m,n] = alpha * sum_k A[m,k] * B[k,n]   (B row-major [K,N];
//              transposed into smem at load time)
// 2-level batch via blockIdx.z -> (outer, inner) with pointer strides.
// ---------------------------------------------------------------------------
template<int BM, int BN, int WM, int WN, bool BT>
__global__ __launch_bounds__((BM/WM)*(BN/WN)*32) void gemm_tf32(
    const float* __restrict__ A, const float* __restrict__ Bm, float* __restrict__ C,
    int K, int lda, int ldb, int ldc, float alpha, int innerCount,
    long aSO, long aSI, long bSO, long bSI, long cSO, long cSI)
{
    constexpr int BK      = 16;
    constexpr int WARPS_M = BM / WM;
    constexpr int WARPS_N = BN / WN;
    constexpr int NT      = WARPS_M * WARPS_N * 32;
    constexpr int MT      = WM / 16;   // mma tiles along M per warp
    constexpr int NTL     = WN / 8;    // mma tiles along N per warp

    const int bz = blockIdx.z;
    const int bo = bz / innerCount, bi = bz % innerCount;
    A  += (long)bo*aSO + (long)bi*aSI;
    Bm += (long)bo*bSO + (long)bi*bSI;
    C  += (long)bo*cSO + (long)bi*cSI;

    __shared__ uint32_t As[BK][BM + 4];
    __shared__ uint32_t Bs[BK][BN + 4];

    const int tid  = threadIdx.x;
    const int lane = tid & 31;
    const int w    = tid >> 5;
    const int wm   = w % WARPS_M;
    const int wn   = w / WARPS_M;
    const int grp  = lane >> 2;     // 0..7
    const int tig  = lane & 3;      // 0..3

    const int row0 = blockIdx.y * BM;
    const int col0 = blockIdx.x * BN;

    float acc[MT][NTL][4];
#pragma unroll
    for (int i = 0; i < MT; i++)
#pragma unroll
        for (int j = 0; j < NTL; j++)
#pragma unroll
            for (int e = 0; e < 4; e++) acc[i][j][e] = 0.0f;

    for (int k0 = 0; k0 < K; k0 += BK) {
        // --- load A tile: BM x BK, scatter to As[k][m] (tf32-converted) ---
#pragma unroll
        for (int it = 0; it < (BM * 4) / NT; it++) {
            int j  = tid + it * NT;
            int m  = j >> 2;
            int kq = (j & 3) * 4;
            float4 t = *reinterpret_cast<const float4*>(&A[(long)(row0 + m) * lda + k0 + kq]);
            As[kq + 0][m] = f2tf32(t.x);
            As[kq + 1][m] = f2tf32(t.y);
            As[kq + 2][m] = f2tf32(t.z);
            As[kq + 3][m] = f2tf32(t.w);
        }
        // --- load B tile ---
        if (BT) {
#pragma unroll
            for (int it = 0; it < (BN * 4) / NT; it++) {
                int j  = tid + it * NT;
                int n  = j >> 2;
                int kq = (j & 3) * 4;
                float4 t = *reinterpret_cast<const float4*>(&Bm[(long)(col0 + n) * ldb + k0 + kq]);
                Bs[kq + 0][n] = f2tf32(t.x);
                Bs[kq + 1][n] = f2tf32(t.y);
                Bs[kq + 2][n] = f2tf32(t.z);
                Bs[kq + 3][n] = f2tf32(t.w);
            }
        } else {
#pragma unroll
            for (int it = 0; it < (BN * 4) / NT; it++) {
                int j  = tid + it * NT;
                int k  = j / (BN / 4);
                int nq = (j % (BN / 4)) * 4;
                float4 t = *reinterpret_cast<const float4*>(&Bm[(long)(k0 + k) * ldb + col0 + nq]);
                uint4 s;
                s.x = f2tf32(t.x); s.y = f2tf32(t.y); s.z = f2tf32(t.z); s.w = f2tf32(t.w);
                *reinterpret_cast<uint4*>(&Bs[k][nq]) = s;
            }
        }
        __syncthreads();

        // --- two k8 steps of mma ---
#pragma unroll
        for (int ks = 0; ks < BK; ks += 8) {
            uint32_t af[MT][4];
            uint32_t bf[NTL][2];
#pragma unroll
            for (int im = 0; im < MT; im++) {
                int r = wm * WM + im * 16 + grp;
                af[im][0] = As[ks + tig    ][r];
                af[im][1] = As[ks + tig    ][r + 8];
                af[im][2] = As[ks + tig + 4][r];
                af[im][3] = As[ks + tig + 4][r + 8];
            }
#pragma unroll
            for (int in = 0; in < NTL; in++) {
                int cc = wn * WN + in * 8 + grp;
                bf[in][0] = Bs[ks + tig    ][cc];
                bf[in][1] = Bs[ks + tig + 4][cc];
            }
#pragma unroll
            for (int im = 0; im < MT; im++)
#pragma unroll
                for (int in = 0; in < NTL; in++)
                    mma16n8k8(acc[im][in], af[im], bf[in]);
        }
        __syncthreads();
    }

    // --- epilogue: float2 stores ---
#pragma unroll
    for (int im = 0; im < MT; im++) {
        int r = row0 + wm * WM + im * 16 + grp;
#pragma unroll
        for (int in = 0; in < NTL; in++) {
            int cc = col0 + wn * WN + in * 8 + 2 * tig;
            float2 lo, hi;
            lo.x = alpha * acc[im][in][0];
            lo.y = alpha * acc[im][in][1];
            hi.x = alpha * acc[im][in][2];
            hi.y = alpha * acc[im][in][3];
            *reinterpret_cast<float2*>(&C[(long)r       * ldc + cc]) = lo;
            *reinterpret_cast<float2*>(&C[(long)(r + 8) * ldc + cc]) = hi;
        }
    }
}

// ---------------------------------------------------------------------------
// Row softmax in place. One block (256 thr) per row of length T_=2048.
// ---------------------------------------------------------------------------
__global__ __launch_bounds__(256) void softmax_rows(float* __restrict__ W)
{
    __shared__ float sred[8];
    const long row = blockIdx.x;
    float* p = W + row * (long)T_;
    const int tid = threadIdx.x;

    float v[8];
#pragma unroll
    for (int i = 0; i < 8; i++) v[i] = p[tid + 256 * i];

    float m = v[0];
#pragma unroll
    for (int i = 1; i < 8; i++) m = fmaxf(m, v[i]);
#pragma unroll
    for (int o = 16; o > 0; o >>= 1) m = fmaxf(m, __shfl_xor_sync(0xffffffffu, m, o));
    if ((tid & 31) == 0) sred[tid >> 5] = m;
    __syncthreads();
    float bm = sred[0];
#pragma unroll
    for (int i = 1; i < 8; i++) bm = fmaxf(bm, sred[i]);
    __syncthreads();

    float s = 0.0f;
#pragma unroll
    for (int i = 0; i < 8; i++) { v[i] = __expf(v[i] - bm); s += v[i]; }
#pragma unroll
    for (int o = 16; o > 0; o >>= 1) s += __shfl_xor_sync(0xffffffffu, s, o);
    if ((tid & 31) == 0) sred[tid >> 5] = s;
    __syncthreads();
    float bs = 0.0f;
#pragma unroll
    for (int i = 0; i < 8; i++) bs += sred[i];

    const float inv = 1.0f / bs;
#pragma unroll
    for (int i = 0; i < 8; i++) p[tid + 256 * i] = v[i] * inv;
}

// ---------------------------------------------------------------------------
extern "C" void kernel_launch(void* const* d_in, const int* in_sizes, int n_in,
                              void* d_out, int out_size)
{
    const float* q  = (const float*)d_in[0];
    const float* k  = (const float*)d_in[1];
    const float* v  = (const float*)d_in[2];
    const float* Wq = (const float*)d_in[3];
    const float* Wk = (const float*)d_in[4];
    const float* Wv = (const float*)d_in[5];
    const float* Wo = (const float*)d_in[6];
    float* out = (float*)d_out;

    float *gq, *gk, *gv, *ga, *gwf;
    cudaGetSymbolAddress((void**)&gq,  g_Q);
    cudaGetSymbolAddress((void**)&gk,  g_K);
    cudaGetSymbolAddress((void**)&gv,  g_V);
    cudaGetSymbolAddress((void**)&ga,  g_attn);
    cudaGetSymbolAddress((void**)&gwf, g_wts_fallback);

    const long outElems = (long)B_ * T_ * D_;
    const long wtsElems = (long)B_ * H_ * T_ * T_;
    float* wts = ((long)out_size >= outElems + wtsElems) ? (out + outElems) : gwf;

    const long TT = (long)T_ * T_;

    // 1) Projections: X[4096,768] @ W^T  (NT, tensor cores)
    dim3 gProj(D_/128, MTOK/128, 1);
    gemm_tf32<128,128,64,32,true><<<gProj, 256>>>(q, Wq, gq, D_, D_, D_, D_, 1.0f, 1, 0,0, 0,0, 0,0);
    gemm_tf32<128,128,64,32,true><<<gProj, 256>>>(k, Wk, gk, D_, D_, D_, D_, 1.0f, 1, 0,0, 0,0, 0,0);
    gemm_tf32<128,128,64,32,true><<<gProj, 256>>>(v, Wv, gv, D_, D_, D_, D_, 1.0f, 1, 0,0, 0,0, 0,0);

    // 2) Scores: per (b,h): S = (Q_h K_h^T) / 8   [2048,2048], K=64
    dim3 gScore(T_/128, T_/128, B_*H_);
    gemm_tf32<128,128,64,32,true><<<gScore, 256>>>(gq, gk, wts,
                              DK_, D_, D_, T_, 0.125f, H_,
                              (long)T_*D_, DK_,
                              (long)T_*D_, DK_,
                              (long)H_*TT, TT);

    // 3) Softmax each of B*H*T rows (in place)
    softmax_rows<<<(unsigned)(B_*H_*T_), 256>>>(wts);

    // 4) attn = W @ V : per (b,h): [2048,2048] @ [2048,64]  (NN)
    dim3 gAV(DK_/64, T_/128, B_*H_);
    gemm_tf32<128,64,32,32,false><<<gAV, 256>>>(wts, gv, ga,
                           T_, T_, D_, D_, 1.0f, H_,
                           (long)H_*TT, TT,
                           (long)T_*D_, DK_,
                           (long)T_*D_, DK_);

    // 5) Output projection: attn[4096,768] @ W_o^T -> out
    gemm_tf32<128,128,64,32,true><<<gProj, 256>>>(ga, Wo, out, D_, D_, D_, D_, 1.0f, 1, 0,0, 0,0, 0,0);
}